// round 12
// baseline (speedup 1.0000x reference)
#include <cuda_runtime.h>
#include <cuda_fp16.h>
#include <cfloat>
#include <cstdint>

#define N_POINTS 32768
#define DIM      256
#define D4       (DIM / 4)
#define K_CODES  4096
#define BM       64
#define BN       64
#define NTILE    (K_CODES / BN)       // 64
#define NCHUNK   (NTILE * 4)          // 256 chunks of 64 dims
#define THREADS  256
#define MARGIN   6e-3f
#define CLB      8
#define KSPLIT   4
#define CLTC     32
#define CLGRID   512

// mma smem layout (bytes): csq 16K + A 32K + B 2x8K = 64 KB -> 3 CTAs/SM
#define SM_CSQ  0
#define SM_A    16384
#define SM_B    49152
#define SMEM_DYN 65536

// cleanup smem (floats): sx[8][260], 2 x sc[32][260]
#define CL_SX_F   (CLB * 260)
#define CL_BUF_F  (CLTC * 260)
#define CL_SMEM   ((CL_SX_F + 2 * CL_BUF_F) * 4)   // 74880 B

typedef unsigned int uint32;
typedef unsigned long long ull;

// ---------------------------------------------------------------------------
__device__ float  g_csq[K_CODES];
__device__ int    g_idx[N_POINTS];
__device__ double g_acc;
__device__ int    g_nflag;
__device__ uint32 g_done;
__device__ int    g_flag[N_POINTS];
__device__ ull    g_pack[N_POINTS];
__device__ __align__(128) __half g_cbh[K_CODES * DIM];

// ---------------------------------------------------------------------------
__device__ __forceinline__ uint32 smem_u32(const void* p) {
    return (uint32)__cvta_generic_to_shared(p);
}
__device__ __forceinline__ void cp_async16(uint32 dst, const void* src) {
    asm volatile("cp.async.cg.shared.global [%0], [%1], 16;" :: "r"(dst), "l"(src));
}
#define CP_COMMIT()  asm volatile("cp.async.commit_group;" ::: "memory")
#define CP_WAIT(n)   asm volatile("cp.async.wait_group %0;" :: "n"(n) : "memory")
#define BAR_SYNC(id) asm volatile("bar.sync %0, 128;" :: "r"(id) : "memory")

__device__ __forceinline__ void ldsm4(uint32* r, uint32 addr) {
    asm volatile("ldmatrix.sync.aligned.m8n8.x4.shared.b16 {%0,%1,%2,%3}, [%4];"
                 : "=r"(r[0]), "=r"(r[1]), "=r"(r[2]), "=r"(r[3]) : "r"(addr));
}
__device__ __forceinline__ void mma16816(float* d, const uint32* a, const uint32* b) {
    asm volatile("mma.sync.aligned.m16n8k16.row.col.f32.f16.f16.f32 "
                 "{%0,%1,%2,%3}, {%4,%5,%6,%7}, {%8,%9}, {%0,%1,%2,%3};"
                 : "+f"(d[0]), "+f"(d[1]), "+f"(d[2]), "+f"(d[3])
                 : "r"(a[0]), "r"(a[1]), "r"(a[2]), "r"(a[3]), "r"(b[0]), "r"(b[1]));
}
__device__ __forceinline__ ull score_key(float s, int idx) {
    uint32 u = __float_as_uint(s);
    u = (u & 0x80000000u) ? ~u : (u | 0x80000000u);
    return ((ull)u << 32) | (uint32)idx;
}

// ---------------------------------------------------------------------------
// Fused prep: reset scalars + csq rowsum + fp32->fp16 codebook convert.
__global__ void vq_prep_kernel(const float* __restrict__ cb) {
    int row = blockIdx.x;
    int tid = threadIdx.x;
    if (row == 0 && tid == 0) { g_acc = 0.0; g_nflag = 0; g_done = 0; }
    float4 v = reinterpret_cast<const float4*>(cb + (size_t)row * DIM)[tid];
    // fp16 convert (same __float2half_rn values as before)
    __half h[4];
    h[0] = __float2half_rn(v.x); h[1] = __float2half_rn(v.y);
    h[2] = __float2half_rn(v.z); h[3] = __float2half_rn(v.w);
    *reinterpret_cast<uint2*>(&g_cbh[(size_t)row * DIM + tid * 4]) =
        *reinterpret_cast<uint2*>(h);
    float s = v.x * v.x + v.y * v.y + v.z * v.z + v.w * v.w;
    #pragma unroll
    for (int o = 16; o > 0; o >>= 1) s += __shfl_xor_sync(0xffffffffu, s, o);
    __shared__ float ws[2];
    if ((tid & 31) == 0) ws[tid >> 5] = s;
    __syncthreads();
    if (tid == 0) g_csq[row] = ws[0] + ws[1];
}

// ---------------------------------------------------------------------------
// Half-CTA chunk load: half wn loads its 32 codes (4 KB).
__device__ __forceinline__ void load_chunk_half(uint32 smB, int it, int wn, int hr) {
    const int tile = it >> 2, kc = it & 3;
    const uint32 dst = smB + (uint32)(it & 1) * 8192;
    const __half* src = g_cbh + (size_t)tile * BN * DIM + kc * 64;
    #pragma unroll
    for (int r = 0; r < 2; r++) {
        int s = hr + r * 128;                 // 0..255 within half
        int cl = s >> 3, seg = s & 7;
        int code = wn * 32 + cl;
        uint32 off = code * 128 + ((seg * 16) ^ ((code & 7) << 4));
        cp_async16(dst + off, src + (size_t)code * DIM + seg * 8);
    }
}

// ---------------------------------------------------------------------------
// 1-pass fp16 tensor-core argmin. BM=64, BN=64, warp tile m16 x n32,
// 64 KB smem -> 3 CTAs/SM (6 warps/SMSP) for issue eligibility.
__global__ __launch_bounds__(THREADS, 3)
void vq_mma_kernel(const float* __restrict__ x) {
    extern __shared__ unsigned char smb[];
    const uint32 sbase = smem_u32(smb);
    float* sCsq = reinterpret_cast<float*>(smb + SM_CSQ);

    const int tid  = threadIdx.x;
    const int lane = tid & 31;
    const int warp = tid >> 5;
    const int wm   = warp >> 1;               // 0..3 -> rows wm*16..+15
    const int wn   = warp & 1;                // 0..1 -> codes wn*32..+31
    const int hr   = (warp >> 1) * 32 + lane; // rank within half (0..127)
    const int barid = wn + 1;
    const int pbase = blockIdx.x * BM;

    load_chunk_half(sbase + SM_B, 0, wn, hr);
    CP_COMMIT();

    for (int i = tid; i < K_CODES; i += THREADS) sCsq[i] = g_csq[i];

    // A tile: 64 pts x 256 dims -> fp16, swizzled rows of 512 B
    {
        const float4* xg = reinterpret_cast<const float4*>(x + (size_t)pbase * DIM);
        #pragma unroll
        for (int i = 0; i < 8; i++) {
            int idx = tid + i * THREADS;       // 0..2047 (row, seg16B)
            int row = idx >> 5, seg = idx & 31;
            float4 v0 = xg[row * 64 + seg * 2];
            float4 v1 = xg[row * 64 + seg * 2 + 1];
            __half h[8];
            h[0] = __float2half_rn(v0.x); h[1] = __float2half_rn(v0.y);
            h[2] = __float2half_rn(v0.z); h[3] = __float2half_rn(v0.w);
            h[4] = __float2half_rn(v1.x); h[5] = __float2half_rn(v1.y);
            h[6] = __float2half_rn(v1.z); h[7] = __float2half_rn(v1.w);
            uint32 off = row * 512 + ((seg * 16) ^ ((row & 7) << 4));
            *reinterpret_cast<uint4*>(smb + SM_A + off) = *reinterpret_cast<uint4*>(h);
        }
    }

    // Fragment addressing
    const uint32 a_row  = wm * 16 + (lane & 7) + ((lane >> 3) & 1) * 8;
    const uint32 a_k16  = ((lane >> 4) & 1) * 16;
    const uint32 swz    = (lane & 7) << 4;
    const uint32 aBase  = sbase + SM_A + a_row * 512;
    const uint32 b_cloc = ((lane >> 4) & 1) * 8 + (lane & 7);
    const uint32 b_k16  = ((lane >> 3) & 1) * 16;

    float dacc[4][4];
    #pragma unroll
    for (int nf = 0; nf < 4; nf++)
        #pragma unroll
        for (int q = 0; q < 4; q++) dacc[nf][q] = 0.f;

    // Per-thread argmin state: 2 row-slots (q)
    float best[2] = {FLT_MAX, FLT_MAX};
    float sec [2] = {FLT_MAX, FLT_MAX};
    int   bidx[2] = {0, 0};

    __syncthreads();       // A + csq visible

    for (int it = 0; it < NCHUNK; it++) {
        const int tile = it >> 2, kc = it & 3;

        BAR_SYNC(barid);   // own half's readers of buf[(it+1)&1] done
        if (it + 1 < NCHUNK) load_chunk_half(sbase + SM_B, it + 1, wn, hr);
        CP_COMMIT();
        CP_WAIT(1);
        BAR_SYNC(barid);   // chunk `it` visible to whole half

        const uint32 bBase = sbase + SM_B + (uint32)(it & 1) * 8192;

        #pragma unroll
        for (int ks = 0; ks < 4; ks++) {
            uint32 a0[4];
            uint32 aoff = ((uint32)(kc * 128 + ks * 32) + a_k16) ^ swz;
            ldsm4(a0, aBase + aoff);
            uint32 boff = ((uint32)(ks * 32) + b_k16) ^ swz;
            #pragma unroll
            for (int np = 0; np < 2; np++) {
                uint32 bh[4];
                ldsm4(bh, bBase + (uint32)(wn * 32 + np * 16 + b_cloc) * 128 + boff);
                mma16816(dacc[2 * np],     a0, bh);
                mma16816(dacc[2 * np + 1], a0, bh + 2);
            }
        }

        if (kc == 3) {
            const int cb0 = tile * BN + wn * 32 + (lane & 3) * 2;
            float cs0v[4], cs1v[4];
            #pragma unroll
            for (int nf = 0; nf < 4; nf++) {
                float2 c2 = *reinterpret_cast<const float2*>(&sCsq[cb0 + nf * 8]);
                cs0v[nf] = c2.x; cs1v[nf] = c2.y;
            }
            #pragma unroll
            for (int q = 0; q < 2; q++) {
                float s[8];
                float tmin = FLT_MAX;
                #pragma unroll
                for (int nf = 0; nf < 4; nf++) {
                    float s0 = fmaf(-2.f, dacc[nf][2 * q],     cs0v[nf]);
                    float s1 = fmaf(-2.f, dacc[nf][2 * q + 1], cs1v[nf]);
                    s[2 * nf] = s0; s[2 * nf + 1] = s1;
                    tmin = fminf(tmin, fminf(s0, s1));
                    dacc[nf][2 * q] = 0.f; dacc[nf][2 * q + 1] = 0.f;
                }
                if (tmin <= sec[q]) {
                    #pragma unroll
                    for (int e = 0; e < 8; e++) {       // ascending ci
                        float sv = s[e];
                        int   ci = cb0 + (e >> 1) * 8 + (e & 1);
                        if (sv < best[q]) { sec[q] = best[q]; best[q] = sv; bidx[q] = ci; }
                        else if (sv < sec[q]) sec[q] = sv;
                    }
                }
            }
        }
    }

    // Quad-lane merge (lane&3 vary codes, same rows)
    float mb[2], ms[2];
    int   mi_[2];
    #pragma unroll
    for (int q = 0; q < 2; q++) {
        float b = best[q], s = sec[q];
        int   i = bidx[q];
        #pragma unroll
        for (int off = 1; off <= 2; off <<= 1) {
            float ob = __shfl_xor_sync(0xffffffffu, b, off);
            float os = __shfl_xor_sync(0xffffffffu, s, off);
            int   oi = __shfl_xor_sync(0xffffffffu, i, off);
            if (ob < b)      { s = fminf(b, os); b = ob; i = oi; }
            else if (b < ob) { s = fminf(s, ob); }
            else             { s = b; i = min(i, oi); }
        }
        mb[q] = b; ms[q] = s; mi_[q] = i;
    }

    // Cross-wn merge via smem (B region; all cp.async retired by now)
    float* mB = reinterpret_cast<float*>(smb + SM_B);     // [2][64]
    float* mS = mB + 128;
    int*   mI = reinterpret_cast<int*>(mS + 128);
    __syncthreads();
    if ((lane & 3) == 0) {
        #pragma unroll
        for (int q = 0; q < 2; q++) {
            int row = wm * 16 + (lane >> 2) + q * 8;      // 0..63
            int s2  = wn * 64 + row;
            mB[s2] = mb[q]; mS[s2] = ms[q]; mI[s2] = mi_[q];
        }
    }
    __syncthreads();
    if (tid < BM) {
        float b0 = mB[tid], s0 = mS[tid], b1 = mB[64 + tid], s1 = mS[64 + tid];
        int   i0 = mI[tid], i1 = mI[64 + tid];
        float b, s; int i;
        if (b0 < b1)      { b = b0; i = i0; s = fminf(s0, b1); }
        else if (b1 < b0) { b = b1; i = i1; s = fminf(s1, b0); }
        else              { b = b0; i = min(i0, i1); s = b0; }
        const int pg = pbase + tid;
        if (s - b <= MARGIN) {
            int pos = atomicAdd(&g_nflag, 1);
            g_flag[pos] = pg;
            g_pack[pos] = 0xFFFFFFFFFFFFFFFFull;
            g_idx[pg]   = -(pos + 1);          // marker: gather reads g_pack
        } else {
            g_idx[pg] = i;
        }
    }
}

// ---------------------------------------------------------------------------
// Exact fp32 resolution (unchanged from round 11 — bits frozen).
__global__ __launch_bounds__(256, 2)
void vq_cleanup_kernel(const float* __restrict__ x, const float* __restrict__ cb) {
    extern __shared__ float clsm[];
    float* sx = clsm;
    float* sc0 = clsm + CL_SX_F;
    const uint32 scb = smem_u32(sc0);
    const int tid  = threadIdx.x;
    const int lane = tid & 31;
    const int w    = tid >> 5;
    const int pt   = lane >> 2;
    const int cit  = w * 4 + (lane & 3);
    const int nf   = g_nflag;
    const int ngroups = (nf + CLB - 1) / CLB;
    const int nwork = ngroups * KSPLIT;

    for (int work = blockIdx.x; work < nwork; work += gridDim.x) {
        const int g     = (work / KSPLIT) * CLB;
        const int cbase = (work % KSPLIT) * (K_CODES / KSPLIT);
        const int npts  = min(CLB, nf - g);
        __syncthreads();
        for (int i = tid; i < npts * D4; i += 256) {
            int p2 = i >> 6, c4 = i & 63;
            int p = g_flag[g + p2];
            *reinterpret_cast<float4*>(&sx[p2 * 260 + c4 * 4]) =
                reinterpret_cast<const float4*>(x)[(size_t)p * D4 + c4];
        }

        #pragma unroll
        for (int r = 0; r < 8; r++) {
            int i = tid + r * 256;
            int cr = i >> 6, seg = i & 63;
            cp_async16(scb + cr * 1040 + seg * 16,
                       cb + (size_t)(cbase + cr) * DIM + seg * 4);
        }
        CP_COMMIT();

        float best = FLT_MAX;
        int   bi   = 0x7fffffff;
        const int ntiles = (K_CODES / KSPLIT) / CLTC;

        for (int t = 0; t < ntiles; t++) {
            __syncthreads();
            if (t + 1 < ntiles) {
                const uint32 dstb = scb + (uint32)((t + 1) & 1) * (CL_BUF_F * 4);
                const float* srcb = cb + (size_t)(cbase + (t + 1) * CLTC) * DIM;
                #pragma unroll
                for (int r = 0; r < 8; r++) {
                    int i = tid + r * 256;
                    int cr = i >> 6, seg = i & 63;
                    cp_async16(dstb + cr * 1040 + seg * 16,
                               srcb + (size_t)cr * DIM + seg * 4);
                }
            }
            CP_COMMIT();
            CP_WAIT(1);
            __syncthreads();

            if (pt < npts) {
                const float* xr = &sx[pt * 260];
                const float* cr = &sc0[(t & 1) * CL_BUF_F + cit * 260];
                float d = 0.f;
                #pragma unroll 16
                for (int k = 0; k < D4; k++) {
                    float4 xv = *reinterpret_cast<const float4*>(&xr[k * 4]);
                    float4 cv = *reinterpret_cast<const float4*>(&cr[k * 4]);
                    d = fmaf(xv.x, cv.x, d); d = fmaf(xv.y, cv.y, d);
                    d = fmaf(xv.z, cv.z, d); d = fmaf(xv.w, cv.w, d);
                }
                const int ci = cbase + t * CLTC + cit;
                float s = fmaf(-2.f, d, __ldg(&g_csq[ci]));
                if (s < best) { best = s; bi = ci; }
            }
        }

        #pragma unroll
        for (int off = 1; off <= 2; off <<= 1) {
            float ob = __shfl_xor_sync(0xffffffffu, best, off);
            int   oi = __shfl_xor_sync(0xffffffffu, bi, off);
            if (ob < best || (ob == best && oi < bi)) { best = ob; bi = oi; }
        }
        if ((lane & 3) == 0 && pt < npts)
            atomicMin(&g_pack[g + pt], score_key(best, bi));
    }
}

// ---------------------------------------------------------------------------
// Gather + loss + (fused) writeback + finalize via last-block-done.
__global__ void vq_gather_kernel(const float* __restrict__ x,
                                 const float* __restrict__ cb,
                                 float* __restrict__ out) {
    const int total4 = N_POINTS * D4;
    float part = 0.f;
    for (int i4 = blockIdx.x * blockDim.x + threadIdx.x; i4 < total4;
         i4 += gridDim.x * blockDim.x) {
        int p  = i4 >> 6;
        int c4 = i4 & 63;
        int ci = g_idx[p];
        if (ci < 0) ci = (int)(g_pack[-ci - 1] & 0xFFFFFFFFull);
        float4 xv = reinterpret_cast<const float4*>(x)[i4];
        float4 qv = reinterpret_cast<const float4*>(cb)[(size_t)ci * D4 + c4];
        float4 d, o;
        d.x = qv.x - xv.x; d.y = qv.y - xv.y; d.z = qv.z - xv.z; d.w = qv.w - xv.w;
        o.x = xv.x + d.x;  o.y = xv.y + d.y;  o.z = xv.z + d.z;  o.w = xv.w + d.w;
        reinterpret_cast<float4*>(out)[i4] = o;
        part += d.x * d.x + d.y * d.y + d.z * d.z + d.w * d.w;
    }
    #pragma unroll
    for (int o = 16; o > 0; o >>= 1) part += __shfl_xor_sync(0xffffffffu, part, o);
    __shared__ float ws[8];
    if ((threadIdx.x & 31) == 0) ws[threadIdx.x >> 5] = part;
    __syncthreads();
    if (threadIdx.x == 0) {
        float bs = 0.f;
        for (int w = 0; w < (int)(blockDim.x >> 5); w++) bs += ws[w];
        atomicAdd(&g_acc, (double)bs);
        __threadfence();
        uint32 t = atomicAdd(&g_done, 1u);
        if (t == gridDim.x - 1) {
            double acc = atomicAdd(&g_acc, 0.0);   // coherent read after all adds
            out[(size_t)N_POINTS * DIM] =
                (float)(1.25 * acc / (double)(N_POINTS * DIM));
        }
    }
}

// ---------------------------------------------------------------------------
extern "C" void kernel_launch(void* const* d_in, const int* in_sizes, int n_in,
                              void* d_out, int out_size) {
    const float* x  = (const float*)d_in[0];
    const float* cb = (const float*)d_in[1];
    float* out = (float*)d_out;
    (void)in_sizes; (void)n_in; (void)out_size;

    cudaFuncSetAttribute(vq_mma_kernel, cudaFuncAttributeMaxDynamicSharedMemorySize,
                         SMEM_DYN);
    cudaFuncSetAttribute(vq_cleanup_kernel, cudaFuncAttributeMaxDynamicSharedMemorySize,
                         CL_SMEM);

    vq_prep_kernel<<<K_CODES, 64>>>(cb);
    vq_mma_kernel<<<N_POINTS / BM, THREADS, SMEM_DYN>>>(x);
    vq_cleanup_kernel<<<CLGRID, 256, CL_SMEM>>>(x, cb);
    vq_gather_kernel<<<4096, 256>>>(x, cb, out);
}

// round 13
// speedup vs baseline: 1.2139x; 1.2139x over previous
#include <cuda_runtime.h>
#include <cuda_fp16.h>
#include <cfloat>
#include <cstdint>

#define N_POINTS 32768
#define DIM      256
#define D4       (DIM / 4)
#define K_CODES  4096
#define BM       128
#define BN       128
#define NTILE    (K_CODES / BN)       // 32
#define NCHUNK   (NTILE * 4)          // 128 chunks of 64 dims
#define THREADS  256
#define MARGIN   6e-3f
#define CLB      8
#define KSPLIT   4
#define CLTC     32
#define CLGRID   512

// mma smem layout (bytes): csq 16K + A 64K + B 2x16K = 112 KB -> 2 CTAs/SM
#define SM_CSQ  0
#define SM_A    16384
#define SM_B    81920
#define SMEM_DYN 114688

// cleanup smem (floats): sx[8][260], 2 x sc[32][260]
#define CL_SX_F   (CLB * 260)
#define CL_BUF_F  (CLTC * 260)
#define CL_SMEM   ((CL_SX_F + 2 * CL_BUF_F) * 4)   // 74880 B

typedef unsigned int uint32;
typedef unsigned long long ull;

// ---------------------------------------------------------------------------
__device__ float  g_csq[K_CODES];
__device__ int    g_idx[N_POINTS];
__device__ double g_acc;
__device__ int    g_nflag;
__device__ uint32 g_done;
__device__ int    g_flag[N_POINTS];
__device__ ull    g_pack[N_POINTS];
__device__ __align__(128) __half g_cbh[K_CODES * DIM];

// ---------------------------------------------------------------------------
__device__ __forceinline__ uint32 smem_u32(const void* p) {
    return (uint32)__cvta_generic_to_shared(p);
}
__device__ __forceinline__ void cp_async16(uint32 dst, const void* src) {
    asm volatile("cp.async.cg.shared.global [%0], [%1], 16;" :: "r"(dst), "l"(src));
}
#define CP_COMMIT()  asm volatile("cp.async.commit_group;" ::: "memory")
#define CP_WAIT(n)   asm volatile("cp.async.wait_group %0;" :: "n"(n) : "memory")
#define BAR_SYNC(id) asm volatile("bar.sync %0, 128;" :: "r"(id) : "memory")

__device__ __forceinline__ void ldsm4(uint32* r, uint32 addr) {
    asm volatile("ldmatrix.sync.aligned.m8n8.x4.shared.b16 {%0,%1,%2,%3}, [%4];"
                 : "=r"(r[0]), "=r"(r[1]), "=r"(r[2]), "=r"(r[3]) : "r"(addr));
}
__device__ __forceinline__ void mma16816(float* d, const uint32* a, const uint32* b) {
    asm volatile("mma.sync.aligned.m16n8k16.row.col.f32.f16.f16.f32 "
                 "{%0,%1,%2,%3}, {%4,%5,%6,%7}, {%8,%9}, {%0,%1,%2,%3};"
                 : "+f"(d[0]), "+f"(d[1]), "+f"(d[2]), "+f"(d[3])
                 : "r"(a[0]), "r"(a[1]), "r"(a[2]), "r"(a[3]), "r"(b[0]), "r"(b[1]));
}
__device__ __forceinline__ ull score_key(float s, int idx) {
    uint32 u = __float_as_uint(s);
    u = (u & 0x80000000u) ? ~u : (u | 0x80000000u);
    return ((ull)u << 32) | (uint32)idx;
}

// ---------------------------------------------------------------------------
// Fused prep: reset scalars + csq rowsum + fp32->fp16 codebook convert.
__global__ void vq_prep_kernel(const float* __restrict__ cb) {
    int row = blockIdx.x;
    int tid = threadIdx.x;
    if (row == 0 && tid == 0) { g_acc = 0.0; g_nflag = 0; g_done = 0; }
    float4 v = reinterpret_cast<const float4*>(cb + (size_t)row * DIM)[tid];
    __half h[4];
    h[0] = __float2half_rn(v.x); h[1] = __float2half_rn(v.y);
    h[2] = __float2half_rn(v.z); h[3] = __float2half_rn(v.w);
    *reinterpret_cast<uint2*>(&g_cbh[(size_t)row * DIM + tid * 4]) =
        *reinterpret_cast<uint2*>(h);
    float s = v.x * v.x + v.y * v.y + v.z * v.z + v.w * v.w;
    #pragma unroll
    for (int o = 16; o > 0; o >>= 1) s += __shfl_xor_sync(0xffffffffu, s, o);
    __shared__ float ws[2];
    if ((tid & 31) == 0) ws[tid >> 5] = s;
    __syncthreads();
    if (tid == 0) g_csq[row] = ws[0] + ws[1];
}

// ---------------------------------------------------------------------------
// Half-CTA chunk load: half wn loads its 64 codes (8 KB).
__device__ __forceinline__ void load_chunk_half(uint32 smB, int it, int wn, int hr) {
    const int tile = it >> 2, kc = it & 3;
    const uint32 dst = smB + (uint32)(it & 1) * 16384;
    const __half* src = g_cbh + (size_t)tile * BN * DIM + kc * 64;
    #pragma unroll
    for (int r = 0; r < 4; r++) {
        int s = hr + r * 128;
        int cl = s >> 3, seg = s & 7;
        int code = wn * 64 + cl;
        uint32 off = code * 128 + ((seg * 16) ^ ((code & 7) << 4));
        cp_async16(dst + off, src + (size_t)code * DIM + seg * 8);
    }
}

// ---------------------------------------------------------------------------
// 1-pass fp16 tensor-core argmin, BM=128/BN=128, warp tile m32 x n64,
// 2 CTAs/SM. (Round-11 kernel; proven 250 us / rel_err 0.0.)
__global__ __launch_bounds__(THREADS, 2)
void vq_mma_kernel(const float* __restrict__ x) {
    extern __shared__ unsigned char smb[];
    const uint32 sbase = smem_u32(smb);
    float* sCsq = reinterpret_cast<float*>(smb + SM_CSQ);

    const int tid  = threadIdx.x;
    const int lane = tid & 31;
    const int warp = tid >> 5;
    const int wm   = warp >> 1;
    const int wn   = warp & 1;
    const int hr   = (warp >> 1) * 32 + lane;
    const int barid = wn + 1;
    const int pbase = blockIdx.x * BM;

    load_chunk_half(sbase + SM_B, 0, wn, hr);
    CP_COMMIT();

    for (int i = tid; i < K_CODES; i += THREADS) sCsq[i] = g_csq[i];

    {
        const float4* xg = reinterpret_cast<const float4*>(x + (size_t)pbase * DIM);
        #pragma unroll
        for (int i = 0; i < 16; i++) {
            int idx = tid + i * THREADS;
            int row = idx >> 5, seg = idx & 31;
            float4 v0 = xg[row * 64 + seg * 2];
            float4 v1 = xg[row * 64 + seg * 2 + 1];
            __half h[8];
            h[0] = __float2half_rn(v0.x); h[1] = __float2half_rn(v0.y);
            h[2] = __float2half_rn(v0.z); h[3] = __float2half_rn(v0.w);
            h[4] = __float2half_rn(v1.x); h[5] = __float2half_rn(v1.y);
            h[6] = __float2half_rn(v1.z); h[7] = __float2half_rn(v1.w);
            uint32 off = row * 512 + ((seg * 16) ^ ((row & 7) << 4));
            *reinterpret_cast<uint4*>(smb + SM_A + off) = *reinterpret_cast<uint4*>(h);
        }
    }

    const uint32 a_row  = wm * 32 + (lane & 7) + ((lane >> 3) & 1) * 8;
    const uint32 a_k16  = ((lane >> 4) & 1) * 16;
    const uint32 swz    = (lane & 7) << 4;
    const uint32 aBase0 = sbase + SM_A + a_row * 512;
    const uint32 aBase1 = aBase0 + 16 * 512;
    const uint32 b_cloc = ((lane >> 4) & 1) * 8 + (lane & 7);
    const uint32 b_k16  = ((lane >> 3) & 1) * 16;

    float dacc[2][8][4];
    #pragma unroll
    for (int mi = 0; mi < 2; mi++)
        #pragma unroll
        for (int nf = 0; nf < 8; nf++)
            #pragma unroll
            for (int q = 0; q < 4; q++) dacc[mi][nf][q] = 0.f;

    float best[4] = {FLT_MAX, FLT_MAX, FLT_MAX, FLT_MAX};
    float sec [4] = {FLT_MAX, FLT_MAX, FLT_MAX, FLT_MAX};
    int   bidx[4] = {0, 0, 0, 0};

    __syncthreads();

    for (int it = 0; it < NCHUNK; it++) {
        const int tile = it >> 2, kc = it & 3;

        BAR_SYNC(barid);
        if (it + 1 < NCHUNK) load_chunk_half(sbase + SM_B, it + 1, wn, hr);
        CP_COMMIT();
        CP_WAIT(1);
        BAR_SYNC(barid);

        const uint32 bBase = sbase + SM_B + (uint32)(it & 1) * 16384;

        #pragma unroll
        for (int ks = 0; ks < 4; ks++) {
            uint32 a0[4], a1[4];
            uint32 aoff = ((uint32)(kc * 128 + ks * 32) + a_k16) ^ swz;
            ldsm4(a0, aBase0 + aoff);
            ldsm4(a1, aBase1 + aoff);
            uint32 boff = ((uint32)(ks * 32) + b_k16) ^ swz;
            #pragma unroll
            for (int np = 0; np < 4; np++) {
                uint32 bh[4];
                ldsm4(bh, bBase + (uint32)(wn * 64 + np * 16 + b_cloc) * 128 + boff);
                mma16816(dacc[0][2 * np],     a0, bh);
                mma16816(dacc[1][2 * np],     a1, bh);
                mma16816(dacc[0][2 * np + 1], a0, bh + 2);
                mma16816(dacc[1][2 * np + 1], a1, bh + 2);
            }
        }

        if (kc == 3) {
            const int cb0 = tile * BN + wn * 64 + (lane & 3) * 2;
            float cs0v[8], cs1v[8];
            #pragma unroll
            for (int nf = 0; nf < 8; nf++) {
                float2 c2 = *reinterpret_cast<const float2*>(&sCsq[cb0 + nf * 8]);
                cs0v[nf] = c2.x; cs1v[nf] = c2.y;
            }
            #pragma unroll
            for (int mi = 0; mi < 2; mi++)
                #pragma unroll
                for (int q = 0; q < 2; q++) {
                    const int k = mi * 2 + q;
                    float s[16];
                    float tmin = FLT_MAX;
                    #pragma unroll
                    for (int nf = 0; nf < 8; nf++) {
                        float s0 = fmaf(-2.f, dacc[mi][nf][2 * q],     cs0v[nf]);
                        float s1 = fmaf(-2.f, dacc[mi][nf][2 * q + 1], cs1v[nf]);
                        s[2 * nf] = s0; s[2 * nf + 1] = s1;
                        tmin = fminf(tmin, fminf(s0, s1));
                        dacc[mi][nf][2 * q] = 0.f; dacc[mi][nf][2 * q + 1] = 0.f;
                    }
                    if (tmin <= sec[k]) {
                        #pragma unroll
                        for (int e = 0; e < 16; e++) {
                            float sv = s[e];
                            int   ci = cb0 + (e >> 1) * 8 + (e & 1);
                            if (sv < best[k]) { sec[k] = best[k]; best[k] = sv; bidx[k] = ci; }
                            else if (sv < sec[k]) sec[k] = sv;
                        }
                    }
                }
        }
    }

    float mb[4], ms[4];
    int   mi_[4];
    #pragma unroll
    for (int k = 0; k < 4; k++) {
        float b = best[k], s = sec[k];
        int   i = bidx[k];
        #pragma unroll
        for (int off = 1; off <= 2; off <<= 1) {
            float ob = __shfl_xor_sync(0xffffffffu, b, off);
            float os = __shfl_xor_sync(0xffffffffu, s, off);
            int   oi = __shfl_xor_sync(0xffffffffu, i, off);
            if (ob < b)      { s = fminf(b, os); b = ob; i = oi; }
            else if (b < ob) { s = fminf(s, ob); }
            else             { s = b; i = min(i, oi); }
        }
        mb[k] = b; ms[k] = s; mi_[k] = i;
    }

    float* mB = reinterpret_cast<float*>(smb + SM_B);
    float* mS = mB + 256;
    int*   mI = reinterpret_cast<int*>(mS + 256);
    __syncthreads();
    if ((lane & 3) == 0) {
        #pragma unroll
        for (int k = 0; k < 4; k++) {
            int row = wm * 32 + (k >> 1) * 16 + (lane >> 2) + (k & 1) * 8;
            int s2  = wn * 128 + row;
            mB[s2] = mb[k]; mS[s2] = ms[k]; mI[s2] = mi_[k];
        }
    }
    __syncthreads();
    if (tid < BM) {
        float b0 = mB[tid], s0 = mS[tid], b1 = mB[128 + tid], s1 = mS[128 + tid];
        int   i0 = mI[tid], i1 = mI[128 + tid];
        float b, s; int i;
        if (b0 < b1)      { b = b0; i = i0; s = fminf(s0, b1); }
        else if (b1 < b0) { b = b1; i = i1; s = fminf(s1, b0); }
        else              { b = b0; i = min(i0, i1); s = b0; }
        const int pg = pbase + tid;
        if (s - b <= MARGIN) {
            int pos = atomicAdd(&g_nflag, 1);
            g_flag[pos] = pg;
            g_pack[pos] = 0xFFFFFFFFFFFFFFFFull;
            g_idx[pg]   = -(pos + 1);          // marker: gather reads g_pack
        } else {
            g_idx[pg] = i;
        }
    }
}

// ---------------------------------------------------------------------------
// Exact fp32 resolution (round-11 version — bits frozen).
__global__ __launch_bounds__(256, 2)
void vq_cleanup_kernel(const float* __restrict__ x, const float* __restrict__ cb) {
    extern __shared__ float clsm[];
    float* sx = clsm;
    float* sc0 = clsm + CL_SX_F;
    const uint32 scb = smem_u32(sc0);
    const int tid  = threadIdx.x;
    const int lane = tid & 31;
    const int w    = tid >> 5;
    const int pt   = lane >> 2;
    const int cit  = w * 4 + (lane & 3);
    const int nf   = g_nflag;
    const int ngroups = (nf + CLB - 1) / CLB;
    const int nwork = ngroups * KSPLIT;

    for (int work = blockIdx.x; work < nwork; work += gridDim.x) {
        const int g     = (work / KSPLIT) * CLB;
        const int cbase = (work % KSPLIT) * (K_CODES / KSPLIT);
        const int npts  = min(CLB, nf - g);
        __syncthreads();
        for (int i = tid; i < npts * D4; i += 256) {
            int p2 = i >> 6, c4 = i & 63;
            int p = g_flag[g + p2];
            *reinterpret_cast<float4*>(&sx[p2 * 260 + c4 * 4]) =
                reinterpret_cast<const float4*>(x)[(size_t)p * D4 + c4];
        }

        #pragma unroll
        for (int r = 0; r < 8; r++) {
            int i = tid + r * 256;
            int cr = i >> 6, seg = i & 63;
            cp_async16(scb + cr * 1040 + seg * 16,
                       cb + (size_t)(cbase + cr) * DIM + seg * 4);
        }
        CP_COMMIT();

        float best = FLT_MAX;
        int   bi   = 0x7fffffff;
        const int ntiles = (K_CODES / KSPLIT) / CLTC;

        for (int t = 0; t < ntiles; t++) {
            __syncthreads();
            if (t + 1 < ntiles) {
                const uint32 dstb = scb + (uint32)((t + 1) & 1) * (CL_BUF_F * 4);
                const float* srcb = cb + (size_t)(cbase + (t + 1) * CLTC) * DIM;
                #pragma unroll
                for (int r = 0; r < 8; r++) {
                    int i = tid + r * 256;
                    int cr = i >> 6, seg = i & 63;
                    cp_async16(dstb + cr * 1040 + seg * 16,
                               srcb + (size_t)cr * DIM + seg * 4);
                }
            }
            CP_COMMIT();
            CP_WAIT(1);
            __syncthreads();

            if (pt < npts) {
                const float* xr = &sx[pt * 260];
                const float* cr = &sc0[(t & 1) * CL_BUF_F + cit * 260];
                float d = 0.f;
                #pragma unroll 16
                for (int k = 0; k < D4; k++) {
                    float4 xv = *reinterpret_cast<const float4*>(&xr[k * 4]);
                    float4 cv = *reinterpret_cast<const float4*>(&cr[k * 4]);
                    d = fmaf(xv.x, cv.x, d); d = fmaf(xv.y, cv.y, d);
                    d = fmaf(xv.z, cv.z, d); d = fmaf(xv.w, cv.w, d);
                }
                const int ci = cbase + t * CLTC + cit;
                float s = fmaf(-2.f, d, __ldg(&g_csq[ci]));
                if (s < best) { best = s; bi = ci; }
            }
        }

        #pragma unroll
        for (int off = 1; off <= 2; off <<= 1) {
            float ob = __shfl_xor_sync(0xffffffffu, best, off);
            int   oi = __shfl_xor_sync(0xffffffffu, bi, off);
            if (ob < best || (ob == best && oi < bi)) { best = ob; bi = oi; }
        }
        if ((lane & 3) == 0 && pt < npts)
            atomicMin(&g_pack[g + pt], score_key(best, bi));
    }
}

// ---------------------------------------------------------------------------
// Gather + loss + fused writeback + finalize via last-block-done.
__global__ void vq_gather_kernel(const float* __restrict__ x,
                                 const float* __restrict__ cb,
                                 float* __restrict__ out) {
    const int total4 = N_POINTS * D4;
    float part = 0.f;
    for (int i4 = blockIdx.x * blockDim.x + threadIdx.x; i4 < total4;
         i4 += gridDim.x * blockDim.x) {
        int p  = i4 >> 6;
        int c4 = i4 & 63;
        int ci = g_idx[p];
        if (ci < 0) ci = (int)(g_pack[-ci - 1] & 0xFFFFFFFFull);
        float4 xv = reinterpret_cast<const float4*>(x)[i4];
        float4 qv = reinterpret_cast<const float4*>(cb)[(size_t)ci * D4 + c4];
        float4 d, o;
        d.x = qv.x - xv.x; d.y = qv.y - xv.y; d.z = qv.z - xv.z; d.w = qv.w - xv.w;
        o.x = xv.x + d.x;  o.y = xv.y + d.y;  o.z = xv.z + d.z;  o.w = xv.w + d.w;
        reinterpret_cast<float4*>(out)[i4] = o;
        part += d.x * d.x + d.y * d.y + d.z * d.z + d.w * d.w;
    }
    #pragma unroll
    for (int o = 16; o > 0; o >>= 1) part += __shfl_xor_sync(0xffffffffu, part, o);
    __shared__ float ws[8];
    if ((threadIdx.x & 31) == 0) ws[threadIdx.x >> 5] = part;
    __syncthreads();
    if (threadIdx.x == 0) {
        float bs = 0.f;
        for (int w = 0; w < (int)(blockDim.x >> 5); w++) bs += ws[w];
        atomicAdd(&g_acc, (double)bs);
        __threadfence();
        uint32 t = atomicAdd(&g_done, 1u);
        if (t == gridDim.x - 1) {
            double acc = atomicAdd(&g_acc, 0.0);
            out[(size_t)N_POINTS * DIM] =
                (float)(1.25 * acc / (double)(N_POINTS * DIM));
        }
    }
}

// ---------------------------------------------------------------------------
extern "C" void kernel_launch(void* const* d_in, const int* in_sizes, int n_in,
                              void* d_out, int out_size) {
    const float* x  = (const float*)d_in[0];
    const float* cb = (const float*)d_in[1];
    float* out = (float*)d_out;
    (void)in_sizes; (void)n_in; (void)out_size;

    cudaFuncSetAttribute(vq_mma_kernel, cudaFuncAttributeMaxDynamicSharedMemorySize,
                         SMEM_DYN);
    cudaFuncSetAttribute(vq_cleanup_kernel, cudaFuncAttributeMaxDynamicSharedMemorySize,
                         CL_SMEM);

    vq_prep_kernel<<<K_CODES, 64>>>(cb);
    vq_mma_kernel<<<N_POINTS / BM, THREADS, SMEM_DYN>>>(x);
    vq_cleanup_kernel<<<CLGRID, 256, CL_SMEM>>>(x, cb);
    vq_gather_kernel<<<4096, 256>>>(x, cb, out);
}

// round 14
// speedup vs baseline: 1.3595x; 1.1199x over previous
#include <cuda_runtime.h>
#include <cuda_fp16.h>
#include <cfloat>
#include <cstdint>

#define N_POINTS 32768
#define DIM      256
#define D4       (DIM / 4)
#define K_CODES  4096
#define BM       128
#define BN       128
#define NTILE    (K_CODES / BN)       // 32
#define NCHUNK   (NTILE * 4)          // 128 chunks of 64 dims
#define THREADS  256
#define MARGIN   6e-3f
#define CLB      8
#define KSPLIT   8                    // 512 codes per work item
#define CLTC     64                   // codes per cleanup smem tile
#define CLGRID   592

// mma smem layout (bytes): csq 16K + A 64K + B 2x16K = 112 KB -> 2 CTAs/SM
#define SM_CSQ  0
#define SM_A    16384
#define SM_B    81920
#define SMEM_DYN 114688

// cleanup smem (floats): sx[8][260] + sc[64][260] (single buffer)
#define CL_SX_F   (CLB * 260)          // 2080
#define CL_SMEM   ((CL_SX_F + CLTC * 260) * 4)   // 74880 B -> 2 CTAs/SM

typedef unsigned int uint32;
typedef unsigned long long ull;

// ---------------------------------------------------------------------------
__device__ float  g_csq[K_CODES];
__device__ int    g_idx[N_POINTS];
__device__ double g_acc;
__device__ int    g_nflag;
__device__ uint32 g_done;
__device__ int    g_flag[N_POINTS];
__device__ ull    g_pack[N_POINTS];
__device__ __align__(128) __half g_cbh[K_CODES * DIM];

// ---------------------------------------------------------------------------
__device__ __forceinline__ uint32 smem_u32(const void* p) {
    return (uint32)__cvta_generic_to_shared(p);
}
__device__ __forceinline__ void cp_async16(uint32 dst, const void* src) {
    asm volatile("cp.async.cg.shared.global [%0], [%1], 16;" :: "r"(dst), "l"(src));
}
#define CP_COMMIT()  asm volatile("cp.async.commit_group;" ::: "memory")
#define CP_WAIT(n)   asm volatile("cp.async.wait_group %0;" :: "n"(n) : "memory")
#define BAR_SYNC(id) asm volatile("bar.sync %0, 128;" :: "r"(id) : "memory")

__device__ __forceinline__ void ldsm4(uint32* r, uint32 addr) {
    asm volatile("ldmatrix.sync.aligned.m8n8.x4.shared.b16 {%0,%1,%2,%3}, [%4];"
                 : "=r"(r[0]), "=r"(r[1]), "=r"(r[2]), "=r"(r[3]) : "r"(addr));
}
__device__ __forceinline__ void mma16816(float* d, const uint32* a, const uint32* b) {
    asm volatile("mma.sync.aligned.m16n8k16.row.col.f32.f16.f16.f32 "
                 "{%0,%1,%2,%3}, {%4,%5,%6,%7}, {%8,%9}, {%0,%1,%2,%3};"
                 : "+f"(d[0]), "+f"(d[1]), "+f"(d[2]), "+f"(d[3])
                 : "r"(a[0]), "r"(a[1]), "r"(a[2]), "r"(a[3]), "r"(b[0]), "r"(b[1]));
}
__device__ __forceinline__ ull score_key(float s, int idx) {
    uint32 u = __float_as_uint(s);
    u = (u & 0x80000000u) ? ~u : (u | 0x80000000u);
    return ((ull)u << 32) | (uint32)idx;
}

// ---------------------------------------------------------------------------
// Fused prep: reset scalars + csq rowsum + fp32->fp16 codebook convert.
__global__ void vq_prep_kernel(const float* __restrict__ cb) {
    int row = blockIdx.x;
    int tid = threadIdx.x;
    if (row == 0 && tid == 0) { g_acc = 0.0; g_nflag = 0; g_done = 0; }
    float4 v = reinterpret_cast<const float4*>(cb + (size_t)row * DIM)[tid];
    __half h[4];
    h[0] = __float2half_rn(v.x); h[1] = __float2half_rn(v.y);
    h[2] = __float2half_rn(v.z); h[3] = __float2half_rn(v.w);
    *reinterpret_cast<uint2*>(&g_cbh[(size_t)row * DIM + tid * 4]) =
        *reinterpret_cast<uint2*>(h);
    float s = v.x * v.x + v.y * v.y + v.z * v.z + v.w * v.w;
    #pragma unroll
    for (int o = 16; o > 0; o >>= 1) s += __shfl_xor_sync(0xffffffffu, s, o);
    __shared__ float ws[2];
    if ((tid & 31) == 0) ws[tid >> 5] = s;
    __syncthreads();
    if (tid == 0) g_csq[row] = ws[0] + ws[1];
}

// ---------------------------------------------------------------------------
// Half-CTA chunk load: half wn loads its 64 codes (8 KB).
__device__ __forceinline__ void load_chunk_half(uint32 smB, int it, int wn, int hr) {
    const int tile = it >> 2, kc = it & 3;
    const uint32 dst = smB + (uint32)(it & 1) * 16384;
    const __half* src = g_cbh + (size_t)tile * BN * DIM + kc * 64;
    #pragma unroll
    for (int r = 0; r < 4; r++) {
        int s = hr + r * 128;
        int cl = s >> 3, seg = s & 7;
        int code = wn * 64 + cl;
        uint32 off = code * 128 + ((seg * 16) ^ ((code & 7) << 4));
        cp_async16(dst + off, src + (size_t)code * DIM + seg * 8);
    }
}

// ---------------------------------------------------------------------------
// 1-pass fp16 tensor-core argmin, BM=128/BN=128, warp tile m32 x n64,
// 2 CTAs/SM. (Proven 250 us / rel_err 0.0 — unchanged.)
__global__ __launch_bounds__(THREADS, 2)
void vq_mma_kernel(const float* __restrict__ x) {
    extern __shared__ unsigned char smb[];
    const uint32 sbase = smem_u32(smb);
    float* sCsq = reinterpret_cast<float*>(smb + SM_CSQ);

    const int tid  = threadIdx.x;
    const int lane = tid & 31;
    const int warp = tid >> 5;
    const int wm   = warp >> 1;
    const int wn   = warp & 1;
    const int hr   = (warp >> 1) * 32 + lane;
    const int barid = wn + 1;
    const int pbase = blockIdx.x * BM;

    load_chunk_half(sbase + SM_B, 0, wn, hr);
    CP_COMMIT();

    for (int i = tid; i < K_CODES; i += THREADS) sCsq[i] = g_csq[i];

    {
        const float4* xg = reinterpret_cast<const float4*>(x + (size_t)pbase * DIM);
        #pragma unroll
        for (int i = 0; i < 16; i++) {
            int idx = tid + i * THREADS;
            int row = idx >> 5, seg = idx & 31;
            float4 v0 = xg[row * 64 + seg * 2];
            float4 v1 = xg[row * 64 + seg * 2 + 1];
            __half h[8];
            h[0] = __float2half_rn(v0.x); h[1] = __float2half_rn(v0.y);
            h[2] = __float2half_rn(v0.z); h[3] = __float2half_rn(v0.w);
            h[4] = __float2half_rn(v1.x); h[5] = __float2half_rn(v1.y);
            h[6] = __float2half_rn(v1.z); h[7] = __float2half_rn(v1.w);
            uint32 off = row * 512 + ((seg * 16) ^ ((row & 7) << 4));
            *reinterpret_cast<uint4*>(smb + SM_A + off) = *reinterpret_cast<uint4*>(h);
        }
    }

    const uint32 a_row  = wm * 32 + (lane & 7) + ((lane >> 3) & 1) * 8;
    const uint32 a_k16  = ((lane >> 4) & 1) * 16;
    const uint32 swz    = (lane & 7) << 4;
    const uint32 aBase0 = sbase + SM_A + a_row * 512;
    const uint32 aBase1 = aBase0 + 16 * 512;
    const uint32 b_cloc = ((lane >> 4) & 1) * 8 + (lane & 7);
    const uint32 b_k16  = ((lane >> 3) & 1) * 16;

    float dacc[2][8][4];
    #pragma unroll
    for (int mi = 0; mi < 2; mi++)
        #pragma unroll
        for (int nf = 0; nf < 8; nf++)
            #pragma unroll
            for (int q = 0; q < 4; q++) dacc[mi][nf][q] = 0.f;

    float best[4] = {FLT_MAX, FLT_MAX, FLT_MAX, FLT_MAX};
    float sec [4] = {FLT_MAX, FLT_MAX, FLT_MAX, FLT_MAX};
    int   bidx[4] = {0, 0, 0, 0};

    __syncthreads();

    for (int it = 0; it < NCHUNK; it++) {
        const int tile = it >> 2, kc = it & 3;

        BAR_SYNC(barid);
        if (it + 1 < NCHUNK) load_chunk_half(sbase + SM_B, it + 1, wn, hr);
        CP_COMMIT();
        CP_WAIT(1);
        BAR_SYNC(barid);

        const uint32 bBase = sbase + SM_B + (uint32)(it & 1) * 16384;

        #pragma unroll
        for (int ks = 0; ks < 4; ks++) {
            uint32 a0[4], a1[4];
            uint32 aoff = ((uint32)(kc * 128 + ks * 32) + a_k16) ^ swz;
            ldsm4(a0, aBase0 + aoff);
            ldsm4(a1, aBase1 + aoff);
            uint32 boff = ((uint32)(ks * 32) + b_k16) ^ swz;
            #pragma unroll
            for (int np = 0; np < 4; np++) {
                uint32 bh[4];
                ldsm4(bh, bBase + (uint32)(wn * 64 + np * 16 + b_cloc) * 128 + boff);
                mma16816(dacc[0][2 * np],     a0, bh);
                mma16816(dacc[1][2 * np],     a1, bh);
                mma16816(dacc[0][2 * np + 1], a0, bh + 2);
                mma16816(dacc[1][2 * np + 1], a1, bh + 2);
            }
        }

        if (kc == 3) {
            const int cb0 = tile * BN + wn * 64 + (lane & 3) * 2;
            float cs0v[8], cs1v[8];
            #pragma unroll
            for (int nf = 0; nf < 8; nf++) {
                float2 c2 = *reinterpret_cast<const float2*>(&sCsq[cb0 + nf * 8]);
                cs0v[nf] = c2.x; cs1v[nf] = c2.y;
            }
            #pragma unroll
            for (int mi = 0; mi < 2; mi++)
                #pragma unroll
                for (int q = 0; q < 2; q++) {
                    const int k = mi * 2 + q;
                    float s[16];
                    float tmin = FLT_MAX;
                    #pragma unroll
                    for (int nf = 0; nf < 8; nf++) {
                        float s0 = fmaf(-2.f, dacc[mi][nf][2 * q],     cs0v[nf]);
                        float s1 = fmaf(-2.f, dacc[mi][nf][2 * q + 1], cs1v[nf]);
                        s[2 * nf] = s0; s[2 * nf + 1] = s1;
                        tmin = fminf(tmin, fminf(s0, s1));
                        dacc[mi][nf][2 * q] = 0.f; dacc[mi][nf][2 * q + 1] = 0.f;
                    }
                    if (tmin <= sec[k]) {
                        #pragma unroll
                        for (int e = 0; e < 16; e++) {
                            float sv = s[e];
                            int   ci = cb0 + (e >> 1) * 8 + (e & 1);
                            if (sv < best[k]) { sec[k] = best[k]; best[k] = sv; bidx[k] = ci; }
                            else if (sv < sec[k]) sec[k] = sv;
                        }
                    }
                }
        }
    }

    float mb[4], ms[4];
    int   mi_[4];
    #pragma unroll
    for (int k = 0; k < 4; k++) {
        float b = best[k], s = sec[k];
        int   i = bidx[k];
        #pragma unroll
        for (int off = 1; off <= 2; off <<= 1) {
            float ob = __shfl_xor_sync(0xffffffffu, b, off);
            float os = __shfl_xor_sync(0xffffffffu, s, off);
            int   oi = __shfl_xor_sync(0xffffffffu, i, off);
            if (ob < b)      { s = fminf(b, os); b = ob; i = oi; }
            else if (b < ob) { s = fminf(s, ob); }
            else             { s = b; i = min(i, oi); }
        }
        mb[k] = b; ms[k] = s; mi_[k] = i;
    }

    float* mB = reinterpret_cast<float*>(smb + SM_B);
    float* mS = mB + 256;
    int*   mI = reinterpret_cast<int*>(mS + 256);
    __syncthreads();
    if ((lane & 3) == 0) {
        #pragma unroll
        for (int k = 0; k < 4; k++) {
            int row = wm * 32 + (k >> 1) * 16 + (lane >> 2) + (k & 1) * 8;
            int s2  = wn * 128 + row;
            mB[s2] = mb[k]; mS[s2] = ms[k]; mI[s2] = mi_[k];
        }
    }
    __syncthreads();
    if (tid < BM) {
        float b0 = mB[tid], s0 = mS[tid], b1 = mB[128 + tid], s1 = mS[128 + tid];
        int   i0 = mI[tid], i1 = mI[128 + tid];
        float b, s; int i;
        if (b0 < b1)      { b = b0; i = i0; s = fminf(s0, b1); }
        else if (b1 < b0) { b = b1; i = i1; s = fminf(s1, b0); }
        else              { b = b0; i = min(i0, i1); s = b0; }
        const int pg = pbase + tid;
        if (s - b <= MARGIN) {
            int pos = atomicAdd(&g_nflag, 1);
            g_flag[pos] = pg;
            g_pack[pos] = 0xFFFFFFFFFFFFFFFFull;
            g_idx[pg]   = -(pos + 1);          // marker: gather reads g_pack
        } else {
            g_idx[pg] = i;
        }
    }
}

// ---------------------------------------------------------------------------
// Exact fp32 resolution, v4: work = (8-pt group) x (512-code chunk).
// Tile = 64 codes, single buffer (74.9 KB -> 2 CTAs/SM). Each thread owns
// TWO codes (cit, cit+32) as independent chains -> 2x chain ILP. Every
// per-code dot keeps the frozen sequential x.x,y,z,w dim order; per-thread
// update order is ascending ci, so strict < keeps first-min. atomicMin on
// packed (orderedScore, idx) merges across blocks lexicographically.
__global__ __launch_bounds__(256, 2)
void vq_cleanup_kernel(const float* __restrict__ x, const float* __restrict__ cb) {
    extern __shared__ float clsm[];
    float* sx = clsm;                          // [CLB][260]
    float* sc = clsm + CL_SX_F;                // [CLTC][260]
    const uint32 scb = smem_u32(sc);
    const int tid  = threadIdx.x;
    const int lane = tid & 31;
    const int w    = tid >> 5;
    const int pt   = lane >> 2;                // 0..7
    const int cit  = w * 4 + (lane & 3);       // 0..31
    const int nf   = g_nflag;
    const int ngroups = (nf + CLB - 1) / CLB;
    const int nwork = ngroups * KSPLIT;

    for (int work = blockIdx.x; work < nwork; work += gridDim.x) {
        const int g     = (work / KSPLIT) * CLB;
        const int cbase = (work % KSPLIT) * (K_CODES / KSPLIT);
        const int npts  = min(CLB, nf - g);
        __syncthreads();                       // protect sx/sc reuse across works
        for (int i = tid; i < npts * D4; i += 256) {
            int p2 = i >> 6, c4 = i & 63;
            int p = g_flag[g + p2];
            *reinterpret_cast<float4*>(&sx[p2 * 260 + c4 * 4]) =
                reinterpret_cast<const float4*>(x)[(size_t)p * D4 + c4];
        }

        float best = FLT_MAX;
        int   bi   = 0x7fffffff;
        const int ntiles = (K_CODES / KSPLIT) / CLTC;   // 8

        for (int t = 0; t < ntiles; t++) {
            __syncthreads();                   // readers of sc done
            // 64 rows x 64 16B-segs = 4096 -> 16 per thread
            const float* srcb = cb + (size_t)(cbase + t * CLTC) * DIM;
            #pragma unroll
            for (int r = 0; r < 16; r++) {
                int i = tid + r * 256;
                int cr = i >> 6, seg = i & 63;
                cp_async16(scb + cr * 1040 + seg * 16,
                           srcb + (size_t)cr * DIM + seg * 4);
            }
            CP_COMMIT();
            CP_WAIT(0);
            __syncthreads();

            if (pt < npts) {
                const float* xr = &sx[pt * 260];
                const float* cA = &sc[cit * 260];
                const float* cB = &sc[(cit + 32) * 260];
                float dA = 0.f, dB = 0.f;
                #pragma unroll 16
                for (int k = 0; k < D4; k++) {
                    float4 xv = *reinterpret_cast<const float4*>(&xr[k * 4]);
                    float4 av = *reinterpret_cast<const float4*>(&cA[k * 4]);
                    float4 bv = *reinterpret_cast<const float4*>(&cB[k * 4]);
                    dA = fmaf(xv.x, av.x, dA); dA = fmaf(xv.y, av.y, dA);
                    dA = fmaf(xv.z, av.z, dA); dA = fmaf(xv.w, av.w, dA);
                    dB = fmaf(xv.x, bv.x, dB); dB = fmaf(xv.y, bv.y, dB);
                    dB = fmaf(xv.z, bv.z, dB); dB = fmaf(xv.w, bv.w, dB);
                }
                const int ciA = cbase + t * CLTC + cit;
                const int ciB = ciA + 32;
                float sA = fmaf(-2.f, dA, __ldg(&g_csq[ciA]));
                float sB = fmaf(-2.f, dB, __ldg(&g_csq[ciB]));
                if (sA < best) { best = sA; bi = ciA; }   // A before B: ascending
                if (sB < best) { best = sB; bi = ciB; }
            }
        }

        // Quad merge (same pt, 4 different code lanes), lexicographic
        #pragma unroll
        for (int off = 1; off <= 2; off <<= 1) {
            float ob = __shfl_xor_sync(0xffffffffu, best, off);
            int   oi = __shfl_xor_sync(0xffffffffu, bi, off);
            if (ob < best || (ob == best && oi < bi)) { best = ob; bi = oi; }
        }
        if ((lane & 3) == 0 && pt < npts)
            atomicMin(&g_pack[g + pt], score_key(best, bi));
    }
}

// ---------------------------------------------------------------------------
// Gather + loss + fused writeback + finalize via last-block-done.
__global__ void vq_gather_kernel(const float* __restrict__ x,
                                 const float* __restrict__ cb,
                                 float* __restrict__ out) {
    const int total4 = N_POINTS * D4;
    float part = 0.f;
    for (int i4 = blockIdx.x * blockDim.x + threadIdx.x; i4 < total4;
         i4 += gridDim.x * blockDim.x) {
        int p  = i4 >> 6;
        int c4 = i4 & 63;
        int ci = g_idx[p];
        if (ci < 0) ci = (int)(g_pack[-ci - 1] & 0xFFFFFFFFull);
        float4 xv = reinterpret_cast<const float4*>(x)[i4];
        float4 qv = reinterpret_cast<const float4*>(cb)[(size_t)ci * D4 + c4];
        float4 d, o;
        d.x = qv.x - xv.x; d.y = qv.y - xv.y; d.z = qv.z - xv.z; d.w = qv.w - xv.w;
        o.x = xv.x + d.x;  o.y = xv.y + d.y;  o.z = xv.z + d.z;  o.w = xv.w + d.w;
        reinterpret_cast<float4*>(out)[i4] = o;
        part += d.x * d.x + d.y * d.y + d.z * d.z + d.w * d.w;
    }
    #pragma unroll
    for (int o = 16; o > 0; o >>= 1) part += __shfl_xor_sync(0xffffffffu, part, o);
    __shared__ float ws[8];
    if ((threadIdx.x & 31) == 0) ws[threadIdx.x >> 5] = part;
    __syncthreads();
    if (threadIdx.x == 0) {
        float bs = 0.f;
        for (int w = 0; w < (int)(blockDim.x >> 5); w++) bs += ws[w];
        atomicAdd(&g_acc, (double)bs);
        __threadfence();
        uint32 t = atomicAdd(&g_done, 1u);
        if (t == gridDim.x - 1) {
            double acc = atomicAdd(&g_acc, 0.0);
            out[(size_t)N_POINTS * DIM] =
                (float)(1.25 * acc / (double)(N_POINTS * DIM));
        }
    }
}

// ---------------------------------------------------------------------------
extern "C" void kernel_launch(void* const* d_in, const int* in_sizes, int n_in,
                              void* d_out, int out_size) {
    const float* x  = (const float*)d_in[0];
    const float* cb = (const float*)d_in[1];
    float* out = (float*)d_out;
    (void)in_sizes; (void)n_in; (void)out_size;

    cudaFuncSetAttribute(vq_mma_kernel, cudaFuncAttributeMaxDynamicSharedMemorySize,
                         SMEM_DYN);
    cudaFuncSetAttribute(vq_cleanup_kernel, cudaFuncAttributeMaxDynamicSharedMemorySize,
                         CL_SMEM);

    vq_prep_kernel<<<K_CODES, 64>>>(cb);
    vq_mma_kernel<<<N_POINTS / BM, THREADS, SMEM_DYN>>>(x);
    vq_cleanup_kernel<<<CLGRID, 256, CL_SMEM>>>(x, cb);
    vq_gather_kernel<<<4096, 256>>>(x, cb, out);
}